// round 1
// baseline (speedup 1.0000x reference)
#include <cuda_runtime.h>
#include <math.h>

#define NB   32
#define NP   2048
#define KNN  20
#define HDIM 128
#define HID  256
#define NTOT (NB*NP)
#define EPSBN 1e-5f

// ---------------- scratch (static device globals; no allocation) ----------------
__device__ int   g_nbr[NTOT*KNN];
__device__ float g_h0[(size_t)NTOT*HDIM];
__device__ float g_h1[(size_t)NTOT*HDIM];

// ================================================================= kNN =========
// One warp per query point. Cloud coords + squared norms cached in SMEM.
// Each lane keeps a sorted (ascending) register top-20 over its 64 strided
// candidates; a 20-round warp lexicographic argmin merge produces the global
// top-20 (ties -> lower index, matching jax.lax.top_k).
#define QPB 8           // queries (warps) per block
__global__ void knn_kernel(const float* __restrict__ x)
{
    __shared__ float sx[NP], sy[NP], sz[NP], sq[NP];
    const int b    = blockIdx.x / (NP/QPB);
    const int tile = blockIdx.x % (NP/QPB);
    const int tid  = threadIdx.x;

    const float* xb = x + (size_t)b*NP*3;
    for (int i = tid; i < NP; i += blockDim.x) {
        float a0 = xb[i*3+0], a1 = xb[i*3+1], a2 = xb[i*3+2];
        sx[i] = a0; sy[i] = a1; sz[i] = a2;
        sq[i] = a0*a0 + a1*a1 + a2*a2;   // same 3-term order as reference
    }
    __syncthreads();

    const int warp = tid >> 5, lane = tid & 31;
    const int qi   = tile*QPB + warp;           // local query index in cloud
    const float qx = sx[qi], qy = sy[qi], qz = sz[qi], qs = sq[qi];

    float d[KNN]; int id[KNN];
#pragma unroll
    for (int j = 0; j < KNN; j++) { d[j] = INFINITY; id[j] = -1; }
    float worst = INFINITY;

    for (int c = lane; c < NP; c += 32) {
        float dot  = qx*sx[c] + qy*sy[c] + qz*sz[c];
        float dist = qs + sq[c] - 2.0f*dot;     // matches sq_p + sq_q - 2*dot
        if (dist < worst) {
            float vd = dist; int vi = c;
#pragma unroll
            for (int j = 0; j < KNN; j++) {     // bubble-insert, keeps ascending
                if (vd < d[j]) {
                    float td = d[j]; int ti = id[j];
                    d[j] = vd; id[j] = vi; vd = td; vi = ti;
                }
            }
            worst = d[KNN-1];
        }
    }

    // --- warp merge: 20 rounds of lexicographic argmin over lane heads ---
    const int qglob = b*NP + qi;
    int* outp = g_nbr + (size_t)qglob*KNN;
    for (int j = 0; j < KNN; j++) {
        float v = d[0]; int vi = id[0];
#pragma unroll
        for (int off = 16; off; off >>= 1) {
            float ov = __shfl_down_sync(0xffffffffu, v,  off);
            int   oi = __shfl_down_sync(0xffffffffu, vi, off);
            if (ov < v || (ov == v && (unsigned)oi < (unsigned)vi)) { v = ov; vi = oi; }
        }
        v  = __shfl_sync(0xffffffffu, v,  0);
        vi = __shfl_sync(0xffffffffu, vi, 0);
        if (lane == 0) outp[j] = b*NP + vi;
        if (id[0] == vi && d[0] == v) {         // winner lane pops its head
#pragma unroll
            for (int t = 0; t < KNN-1; t++) { d[t] = d[t+1]; id[t] = id[t+1]; }
            d[KNN-1] = INFINITY; id[KNN-1] = -1;
        }
    }
}

// ============================================================ transfer =========
// h0[n, f] = bt[f] + sum_d x[n,d] * Wt[d,f]
__global__ void transfer_kernel(const float* __restrict__ x,
                                const float* __restrict__ Wt,
                                const float* __restrict__ bt)
{
    int idx = blockIdx.x * blockDim.x + threadIdx.x;     // NTOT*HDIM threads
    int n = idx >> 7, f = idx & (HDIM-1);
    float x0 = x[n*3+0], x1 = x[n*3+1], x2 = x[n*3+2];
    g_h0[idx] = bt[f] + x0*Wt[f] + x1*Wt[HDIM+f] + x2*Wt[2*HDIM+f];
}

// ============================================================ GIN layer ========
// Fused: gather-max over {self + 20 nbrs} -> GEMM1(128->256)+ReLU -> GEMM2(256->128)
// -> BN (+optional ReLU). One block = 64 rows, 512 threads.
#define ROWS 64
#define KT   32
#define LTHREADS 512
#define GIN_SMEM_BYTES (ROWS*HDIM*4 + ROWS*HID*4 + KT*HID*4 + ROWS*KNN*4)  // 136192

__global__ __launch_bounds__(LTHREADS, 1)
void gin_layer_kernel(const float* __restrict__ hin,
                      const float* __restrict__ W1, const float* __restrict__ b1,
                      const float* __restrict__ W2, const float* __restrict__ b2,
                      const float* __restrict__ gw, const float* __restrict__ bb,
                      const float* __restrict__ rm, const float* __restrict__ rv,
                      float* __restrict__ hout, int relu_out)
{
    extern __shared__ float smem[];
    float* s_agg = smem;                       // [64][128]
    float* s_t1  = s_agg + ROWS*HDIM;          // [64][256]
    float* s_w   = s_t1  + ROWS*HID;           // [32][256] (reused [32][128])
    int*   s_nbr = (int*)(s_w + KT*HID);       // [64][20]

    const int tid  = threadIdx.x;
    const int row0 = blockIdx.x * ROWS;

    // ---- stage neighbor lists ----
    for (int i = tid; i < ROWS*KNN; i += LTHREADS)
        s_nbr[i] = g_nbr[(size_t)row0*KNN + i];
    __syncthreads();

    // ---- gather-max (self + 20 neighbors), coalesced 512B rows ----
    {
        const int f = tid & (HDIM-1);
        for (int r = tid >> 7; r < ROWS; r += LTHREADS/HDIM) {
            int row = row0 + r;
            float m = __ldg(&hin[(size_t)row*HDIM + f]);
#pragma unroll 4
            for (int k = 0; k < KNN; k++) {
                int nb = s_nbr[r*KNN + k];
                m = fmaxf(m, __ldg(&hin[(size_t)nb*HDIM + f]));
            }
            s_agg[r*HDIM + f] = m;
        }
    }
    __syncthreads();

    const int tx = tid & 31;      // column lane
    const int ty = tid >> 5;      // warp id = row group (constant per warp -> A broadcast)

    // ---- GEMM1: t1[64][256] = relu(agg @ W1 + b1) ----
    float acc1[4][8];
    {
        float4 b1a = *(const float4*)&b1[tx*4];
        float4 b1b = *(const float4*)&b1[128 + tx*4];
#pragma unroll
        for (int i = 0; i < 4; i++) {
            acc1[i][0]=b1a.x; acc1[i][1]=b1a.y; acc1[i][2]=b1a.z; acc1[i][3]=b1a.w;
            acc1[i][4]=b1b.x; acc1[i][5]=b1b.y; acc1[i][6]=b1b.z; acc1[i][7]=b1b.w;
        }
    }
    for (int kt = 0; kt < HDIM/KT; kt++) {
        const float4* src = (const float4*)(W1 + (size_t)kt*KT*HID);  // contiguous rows
        float4* dst = (float4*)s_w;
        for (int i = tid; i < KT*HID/4; i += LTHREADS) dst[i] = src[i];
        __syncthreads();
#pragma unroll
        for (int kk = 0; kk < KT; kk++) {
            float a[4];
#pragma unroll
            for (int i = 0; i < 4; i++) a[i] = s_agg[(ty*4+i)*HDIM + kt*KT + kk];
#pragma unroll
            for (int g = 0; g < 2; g++) {
                float4 w = *(float4*)&s_w[kk*HID + g*128 + tx*4];
#pragma unroll
                for (int i = 0; i < 4; i++) {
                    acc1[i][g*4+0] += a[i]*w.x;
                    acc1[i][g*4+1] += a[i]*w.y;
                    acc1[i][g*4+2] += a[i]*w.z;
                    acc1[i][g*4+3] += a[i]*w.w;
                }
            }
        }
        __syncthreads();
    }
#pragma unroll
    for (int i = 0; i < 4; i++)
#pragma unroll
        for (int g = 0; g < 2; g++) {
            float4 v = make_float4(fmaxf(acc1[i][g*4+0], 0.f), fmaxf(acc1[i][g*4+1], 0.f),
                                   fmaxf(acc1[i][g*4+2], 0.f), fmaxf(acc1[i][g*4+3], 0.f));
            *(float4*)&s_t1[(ty*4+i)*HID + g*128 + tx*4] = v;
        }
    __syncthreads();

    // ---- GEMM2: out[64][128] = t1 @ W2 + b2 ----
    float acc2[4][4];
    {
        float4 b2v = *(const float4*)&b2[tx*4];
#pragma unroll
        for (int i = 0; i < 4; i++) {
            acc2[i][0]=b2v.x; acc2[i][1]=b2v.y; acc2[i][2]=b2v.z; acc2[i][3]=b2v.w;
        }
    }
    for (int kt = 0; kt < HID/KT; kt++) {
        const float4* src = (const float4*)(W2 + (size_t)kt*KT*HDIM);
        float4* dst = (float4*)s_w;
        for (int i = tid; i < KT*HDIM/4; i += LTHREADS) dst[i] = src[i];
        __syncthreads();
#pragma unroll
        for (int kk = 0; kk < KT; kk++) {
            float a[4];
#pragma unroll
            for (int i = 0; i < 4; i++) a[i] = s_t1[(ty*4+i)*HID + kt*KT + kk];
            float4 w = *(float4*)&s_w[kk*HDIM + tx*4];
#pragma unroll
            for (int i = 0; i < 4; i++) {
                acc2[i][0] += a[i]*w.x;
                acc2[i][1] += a[i]*w.y;
                acc2[i][2] += a[i]*w.z;
                acc2[i][3] += a[i]*w.w;
            }
        }
        __syncthreads();
    }

    // ---- BN (+optional ReLU), coalesced float4 stores ----
    {
        float4 g4  = *(const float4*)&gw[tx*4];
        float4 be4 = *(const float4*)&bb[tx*4];
        float4 rm4 = *(const float4*)&rm[tx*4];
        float4 rv4 = *(const float4*)&rv[tx*4];
        float s0 = g4.x*rsqrtf(rv4.x+EPSBN), s1 = g4.y*rsqrtf(rv4.y+EPSBN);
        float s2 = g4.z*rsqrtf(rv4.z+EPSBN), s3 = g4.w*rsqrtf(rv4.w+EPSBN);
#pragma unroll
        for (int i = 0; i < 4; i++) {
            float4 v;
            v.x = s0*(acc2[i][0]-rm4.x) + be4.x;
            v.y = s1*(acc2[i][1]-rm4.y) + be4.y;
            v.z = s2*(acc2[i][2]-rm4.z) + be4.z;
            v.w = s3*(acc2[i][3]-rm4.w) + be4.w;
            if (relu_out) {
                v.x = fmaxf(v.x, 0.f); v.y = fmaxf(v.y, 0.f);
                v.z = fmaxf(v.z, 0.f); v.w = fmaxf(v.w, 0.f);
            }
            *(float4*)&hout[(size_t)(row0 + ty*4 + i)*HDIM + tx*4] = v;
        }
    }
}

// ================================================================ launch =======
extern "C" void kernel_launch(void* const* d_in, const int* in_sizes, int n_in,
                              void* d_out, int out_size)
{
    const float* x    = (const float*)d_in[0];
    // d_in[1] = batch (unused: equal-size clouds by construction)
    const float* Wt   = (const float*)d_in[2];
    const float* bt   = (const float*)d_in[3];
    const float* W1_0 = (const float*)d_in[4];
    const float* b1_0 = (const float*)d_in[5];
    const float* W2_0 = (const float*)d_in[6];
    const float* b2_0 = (const float*)d_in[7];
    const float* g0   = (const float*)d_in[8];
    const float* be0  = (const float*)d_in[9];
    const float* rm0  = (const float*)d_in[10];
    const float* rv0  = (const float*)d_in[11];
    const float* W1_1 = (const float*)d_in[12];
    const float* b1_1 = (const float*)d_in[13];
    const float* W2_1 = (const float*)d_in[14];
    const float* b2_1 = (const float*)d_in[15];
    const float* g1   = (const float*)d_in[16];
    const float* be1  = (const float*)d_in[17];
    const float* rm1  = (const float*)d_in[18];
    const float* rv1  = (const float*)d_in[19];
    float* out = (float*)d_out;

    cudaFuncSetAttribute(gin_layer_kernel,
                         cudaFuncAttributeMaxDynamicSharedMemorySize, GIN_SMEM_BYTES);

    void *p_h0, *p_h1;
    cudaGetSymbolAddress(&p_h0, g_h0);
    cudaGetSymbolAddress(&p_h1, g_h1);

    // kNN and transfer are independent; layers are sequential.
    knn_kernel<<<NB*(NP/QPB), 256>>>(x);
    transfer_kernel<<<(NTOT*HDIM)/256, 256>>>(x, Wt, bt);

    gin_layer_kernel<<<NTOT/ROWS, LTHREADS, GIN_SMEM_BYTES>>>(
        (const float*)p_h0, W1_0, b1_0, W2_0, b2_0, g0, be0, rm0, rv0,
        (float*)p_h1, /*relu_out=*/1);

    gin_layer_kernel<<<NTOT/ROWS, LTHREADS, GIN_SMEM_BYTES>>>(
        (const float*)p_h1, W1_1, b1_1, W2_1, b2_1, g1, be1, rm1, rv1,
        out, /*relu_out=*/0);
}

// round 3
// speedup vs baseline: 1.5320x; 1.5320x over previous
#include <cuda_runtime.h>
#include <math.h>

#define NB   32
#define NP   2048
#define KNN  20
#define HDIM 128
#define HID  256
#define NTOT (NB*NP)
#define EPSBN 1e-5f

// ---------------- scratch (static device globals; no allocation) ----------------
__device__ int   g_nbr[NTOT*KNN];
__device__ float g_h0[(size_t)NTOT*HDIM];
__device__ float g_h1[(size_t)NTOT*HDIM];

// ---------------- f32x2 packed-FMA helpers (FFMA2; PTX-only pattern) -----------
__device__ __forceinline__ void ffma2(unsigned long long &d,
                                      unsigned long long a, unsigned long long b) {
    asm("fma.rn.f32x2 %0, %1, %2, %0;" : "+l"(d) : "l"(a), "l"(b));
}
__device__ __forceinline__ unsigned long long pack2(float v) {
    unsigned long long r; asm("mov.b64 %0, {%1, %1};" : "=l"(r) : "f"(v)); return r;
}
__device__ __forceinline__ float2 unpack2(unsigned long long v) {
    float2 f; asm("mov.b64 {%0, %1}, %2;" : "=f"(f.x), "=f"(f.y) : "l"(v)); return f;
}

// ================================================================= kNN =========
// One query per THREAD (not warp). All 2048 candidates of the cloud are cached
// in SMEM as float4 (x,y,z,|p|^2); every lane reads the same candidate ->
// LDS.128 broadcast. Filtered sorted insert: expected inserts ~= 20*ln(2048/20)
// ~= 92 of 2048 steps, so the 20-deep bubble is rare.
// Ties: strict '<' keeps earlier (lower) index, matching jax.lax.top_k.
#define KBLK 128
__global__ __launch_bounds__(KBLK)
void knn_kernel(const float* __restrict__ x)
{
    __shared__ float4 sc[NP];                 // 32 KB
    const int b    = blockIdx.x >> 4;         // NP/KBLK = 16 tiles per cloud
    const int tile = blockIdx.x & 15;
    const int tid  = threadIdx.x;

    const float* xb = x + (size_t)b*NP*3;
    for (int i = tid; i < NP; i += KBLK) {
        float a0 = xb[i*3+0], a1 = xb[i*3+1], a2 = xb[i*3+2];
        sc[i] = make_float4(a0, a1, a2, a0*a0 + a1*a1 + a2*a2);
    }
    __syncthreads();

    const int q = tile*KBLK + tid;            // local query index in cloud
    const float4 qc = sc[q];

    float d[KNN]; int id[KNN];
#pragma unroll
    for (int j = 0; j < KNN; j++) { d[j] = INFINITY; id[j] = -1; }
    float worst = INFINITY;

#pragma unroll 2
    for (int c = 0; c < NP; c++) {
        float4 cc = sc[c];
        float dot  = qc.x*cc.x + qc.y*cc.y + qc.z*cc.z;
        float dist = qc.w + cc.w - 2.0f*dot;  // matches sq_p + sq_q - 2*dot
        if (dist < worst) {
            float vd = dist; int vi = c;
#pragma unroll
            for (int j = 0; j < KNN; j++) {   // bubble-insert, keeps ascending
                if (vd < d[j]) {
                    float td = d[j]; int ti = id[j];
                    d[j] = vd; id[j] = vi; vd = td; vi = ti;
                }
            }
            worst = d[KNN-1];
        }
    }

    int* outp = g_nbr + ((size_t)b*NP + q)*KNN;
#pragma unroll
    for (int j = 0; j < KNN; j++) outp[j] = b*NP + id[j];
}

// ============================================================ transfer =========
__global__ void transfer_kernel(const float* __restrict__ x,
                                const float* __restrict__ Wt,
                                const float* __restrict__ bt)
{
    int idx = blockIdx.x * blockDim.x + threadIdx.x;     // NTOT*HDIM threads
    int n = idx >> 7, f = idx & (HDIM-1);
    float x0 = x[n*3+0], x1 = x[n*3+1], x2 = x[n*3+2];
    g_h0[idx] = bt[f] + x0*Wt[f] + x1*Wt[HDIM+f] + x2*Wt[2*HDIM+f];
}

// ============================================================ GIN layer ========
// Fused: gather-max (self + 20 nbrs) -> GEMM1(128->256)+ReLU -> GEMM2(256->128)
// -> BN (+optional ReLU). One block = 64 rows, 512 threads.
// GEMMs use packed fma.rn.f32x2 (2 MACs/issue). KT=64 halves barrier count.
#define ROWS 64
#define KT   64
#define LTHREADS 512
// s_agg 32K + s_t1 64K + s_w 64K + s_nbr 5K
#define GIN_SMEM_BYTES (ROWS*HDIM*4 + ROWS*HID*4 + KT*HID*4 + ROWS*KNN*4)  // 168960

__global__ __launch_bounds__(LTHREADS, 1)
void gin_layer_kernel(const float* __restrict__ hin,
                      const float* __restrict__ W1, const float* __restrict__ b1,
                      const float* __restrict__ W2, const float* __restrict__ b2,
                      const float* __restrict__ gw, const float* __restrict__ bb,
                      const float* __restrict__ rm, const float* __restrict__ rv,
                      float* __restrict__ hout, int relu_out)
{
    extern __shared__ float smem[];
    float* s_agg = smem;                       // [64][128]
    float* s_t1  = s_agg + ROWS*HDIM;          // [64][256]
    float* s_w   = s_t1  + ROWS*HID;           // [64][256] (reused [64][128])
    int*   s_nbr = (int*)(s_w + KT*HID);       // [64][20]

    const int tid  = threadIdx.x;
    const int row0 = blockIdx.x * ROWS;

    // ---- stage neighbor lists ----
    for (int i = tid; i < ROWS*KNN; i += LTHREADS)
        s_nbr[i] = g_nbr[(size_t)row0*KNN + i];
    __syncthreads();

    // ---- gather-max, float4 rows (21 x LDG.128 per row-quarter) ----
    {
        const int lf = tid & 31;               // feature quad: cols lf*4..lf*4+3
        for (int r = tid >> 5; r < ROWS; r += LTHREADS/32) {
            int row = row0 + r;
            float4 m = __ldg((const float4*)&hin[(size_t)row*HDIM + lf*4]);
#pragma unroll 4
            for (int k = 0; k < KNN; k++) {
                int nb = s_nbr[r*KNN + k];
                float4 v = __ldg((const float4*)&hin[(size_t)nb*HDIM + lf*4]);
                m.x = fmaxf(m.x, v.x); m.y = fmaxf(m.y, v.y);
                m.z = fmaxf(m.z, v.z); m.w = fmaxf(m.w, v.w);
            }
            *(float4*)&s_agg[r*HDIM + lf*4] = m;
        }
    }
    __syncthreads();

    const int tx = tid & 31;      // column lane (4 consecutive cols -> 2 pairs)
    const int ty = tid >> 5;      // warp id = row group (A reads broadcast)

    // ---- GEMM1: t1[64][256] = relu(agg @ W1 + b1), packed f32x2 ----
    unsigned long long acc1[4][4];             // 4 rows x 4 col-pairs (8 cols)
    {
        ulonglong2 bA = *(const ulonglong2*)&b1[tx*4];
        ulonglong2 bB = *(const ulonglong2*)&b1[128 + tx*4];
#pragma unroll
        for (int i = 0; i < 4; i++) {
            acc1[i][0]=bA.x; acc1[i][1]=bA.y; acc1[i][2]=bB.x; acc1[i][3]=bB.y;
        }
    }
    for (int kt = 0; kt < HDIM/KT; kt++) {     // 2 stages
        const float4* src = (const float4*)(W1 + (size_t)kt*KT*HID);
        float4* dst = (float4*)s_w;
        for (int i = tid; i < KT*HID/4; i += LTHREADS) dst[i] = src[i];
        __syncthreads();
#pragma unroll 4
        for (int kk4 = 0; kk4 < KT/4; kk4++) {
            float av[4][4];
#pragma unroll
            for (int i = 0; i < 4; i++) {
                float4 t = *(const float4*)&s_agg[(ty*4+i)*HDIM + kt*KT + kk4*4];
                av[0][i]=t.x; av[1][i]=t.y; av[2][i]=t.z; av[3][i]=t.w;
            }
#pragma unroll
            for (int u = 0; u < 4; u++) {
                int kk = kk4*4 + u;
                ulonglong2 wA = *(const ulonglong2*)&s_w[kk*HID + tx*4];
                ulonglong2 wB = *(const ulonglong2*)&s_w[kk*HID + 128 + tx*4];
#pragma unroll
                for (int i = 0; i < 4; i++) {
                    unsigned long long pa = pack2(av[u][i]);
                    ffma2(acc1[i][0], pa, wA.x);
                    ffma2(acc1[i][1], pa, wA.y);
                    ffma2(acc1[i][2], pa, wB.x);
                    ffma2(acc1[i][3], pa, wB.y);
                }
            }
        }
        __syncthreads();
    }
#pragma unroll
    for (int i = 0; i < 4; i++) {
        float2 p0 = unpack2(acc1[i][0]), p1 = unpack2(acc1[i][1]);
        float2 p2 = unpack2(acc1[i][2]), p3 = unpack2(acc1[i][3]);
        float4 v0 = make_float4(fmaxf(p0.x,0.f), fmaxf(p0.y,0.f),
                                fmaxf(p1.x,0.f), fmaxf(p1.y,0.f));
        float4 v1 = make_float4(fmaxf(p2.x,0.f), fmaxf(p2.y,0.f),
                                fmaxf(p3.x,0.f), fmaxf(p3.y,0.f));
        *(float4*)&s_t1[(ty*4+i)*HID + tx*4]       = v0;
        *(float4*)&s_t1[(ty*4+i)*HID + 128 + tx*4] = v1;
    }
    __syncthreads();

    // ---- GEMM2: out[64][128] = t1 @ W2 + b2, packed f32x2 ----
    unsigned long long acc2[4][2];             // 4 rows x 2 col-pairs (4 cols)
    {
        ulonglong2 b2v = *(const ulonglong2*)&b2[tx*4];
#pragma unroll
        for (int i = 0; i < 4; i++) { acc2[i][0]=b2v.x; acc2[i][1]=b2v.y; }
    }
    for (int kt = 0; kt < HID/KT; kt++) {      // 4 stages
        const float4* src = (const float4*)(W2 + (size_t)kt*KT*HDIM);
        float4* dst = (float4*)s_w;
        for (int i = tid; i < KT*HDIM/4; i += LTHREADS) dst[i] = src[i];
        __syncthreads();
#pragma unroll 4
        for (int kk4 = 0; kk4 < KT/4; kk4++) {
            float av[4][4];
#pragma unroll
            for (int i = 0; i < 4; i++) {
                float4 t = *(const float4*)&s_t1[(ty*4+i)*HID + kt*KT + kk4*4];
                av[0][i]=t.x; av[1][i]=t.y; av[2][i]=t.z; av[3][i]=t.w;
            }
#pragma unroll
            for (int u = 0; u < 4; u++) {
                int kk = kk4*4 + u;
                ulonglong2 w = *(const ulonglong2*)&s_w[kk*HDIM + tx*4];
#pragma unroll
                for (int i = 0; i < 4; i++) {
                    unsigned long long pa = pack2(av[u][i]);
                    ffma2(acc2[i][0], pa, w.x);
                    ffma2(acc2[i][1], pa, w.y);
                }
            }
        }
        __syncthreads();
    }

    // ---- BN (+optional ReLU), coalesced float4 stores ----
    {
        float4 g4  = *(const float4*)&gw[tx*4];
        float4 be4 = *(const float4*)&bb[tx*4];
        float4 rm4 = *(const float4*)&rm[tx*4];
        float4 rv4 = *(const float4*)&rv[tx*4];
        float s0 = g4.x*rsqrtf(rv4.x+EPSBN), s1 = g4.y*rsqrtf(rv4.y+EPSBN);
        float s2 = g4.z*rsqrtf(rv4.z+EPSBN), s3 = g4.w*rsqrtf(rv4.w+EPSBN);
#pragma unroll
        for (int i = 0; i < 4; i++) {
            float2 p0 = unpack2(acc2[i][0]), p1 = unpack2(acc2[i][1]);
            float4 v;
            v.x = s0*(p0.x-rm4.x) + be4.x;
            v.y = s1*(p0.y-rm4.y) + be4.y;
            v.z = s2*(p1.x-rm4.z) + be4.z;
            v.w = s3*(p1.y-rm4.w) + be4.w;
            if (relu_out) {
                v.x = fmaxf(v.x, 0.f); v.y = fmaxf(v.y, 0.f);
                v.z = fmaxf(v.z, 0.f); v.w = fmaxf(v.w, 0.f);
            }
            *(float4*)&hout[(size_t)(row0 + ty*4 + i)*HDIM + tx*4] = v;
        }
    }
}

// ================================================================ launch =======
extern "C" void kernel_launch(void* const* d_in, const int* in_sizes, int n_in,
                              void* d_out, int out_size)
{
    const float* x    = (const float*)d_in[0];
    // d_in[1] = batch (unused: equal-size clouds by construction)
    const float* Wt   = (const float*)d_in[2];
    const float* bt   = (const float*)d_in[3];
    const float* W1_0 = (const float*)d_in[4];
    const float* b1_0 = (const float*)d_in[5];
    const float* W2_0 = (const float*)d_in[6];
    const float* b2_0 = (const float*)d_in[7];
    const float* g0   = (const float*)d_in[8];
    const float* be0  = (const float*)d_in[9];
    const float* rm0  = (const float*)d_in[10];
    const float* rv0  = (const float*)d_in[11];
    const float* W1_1 = (const float*)d_in[12];
    const float* b1_1 = (const float*)d_in[13];
    const float* W2_1 = (const float*)d_in[14];
    const float* b2_1 = (const float*)d_in[15];
    const float* g1   = (const float*)d_in[16];
    const float* be1  = (const float*)d_in[17];
    const float* rm1  = (const float*)d_in[18];
    const float* rv1  = (const float*)d_in[19];
    float* out = (float*)d_out;

    cudaFuncSetAttribute(gin_layer_kernel,
                         cudaFuncAttributeMaxDynamicSharedMemorySize, GIN_SMEM_BYTES);

    void *p_h0, *p_h1;
    cudaGetSymbolAddress(&p_h0, g_h0);
    cudaGetSymbolAddress(&p_h1, g_h1);

    knn_kernel<<<NB*(NP/KBLK), KBLK>>>(x);
    transfer_kernel<<<(NTOT*HDIM)/256, 256>>>(x, Wt, bt);

    gin_layer_kernel<<<NTOT/ROWS, LTHREADS, GIN_SMEM_BYTES>>>(
        (const float*)p_h0, W1_0, b1_0, W2_0, b2_0, g0, be0, rm0, rv0,
        (float*)p_h1, /*relu_out=*/1);

    gin_layer_kernel<<<NTOT/ROWS, LTHREADS, GIN_SMEM_BYTES>>>(
        (const float*)p_h1, W1_1, b1_1, W2_1, b2_1, g1, be1, rm1, rv1,
        out, /*relu_out=*/0);
}